// round 8
// baseline (speedup 1.0000x reference)
#include <cuda_runtime.h>
#include <cuda_bf16.h>
#include <math.h>
#include <stdint.h>

// ---------------- problem constants ----------------
#define T_TOK   4096
#define STATE_D 1024
#define EMBED_D 512
#define DIST_D  20
#define HID     1024
#define GI_D    2580      // 2*STATE_D + EMBED_D + DIST_D
#define MAX_W   10
#define NBUCK   9

// ---------------- scratch (static device globals; no allocs) --------------
__device__ float g_h1[(size_t)T_TOK * HID];
__device__ float g_h2[(size_t)T_TOK * HID];
__device__ float g_attns[T_TOK];
__device__ float g_pa[(size_t)T_TOK * HID];
__device__ float g_pb[(size_t)T_TOK * HID];
__device__ float g_ec[(size_t)T_TOK * HID];
__device__ float g_wd[(size_t)NBUCK * HID];
__device__ float g_s1[(size_t)40960 * HID];
__device__ float g_s2[(size_t)40960 * HID];
// tf32-rounded operand copies
__device__ float g_states_t[(size_t)T_TOK * STATE_D];
__device__ float g_embeds_t[(size_t)T_TOK * EMBED_D];
__device__ float g_aW1_t[(size_t)STATE_D * HID];
__device__ float g_aW2_t[(size_t)HID * HID];
__device__ float g_sW1_t[(size_t)2560 * HID];     // rows 0..2559 of sW1
__device__ float g_sW2_t[(size_t)HID * HID];

__device__ __forceinline__ uint32_t f2tf32(float x) {
    uint32_t r;
    asm("cvt.rna.tf32.f32 %0, %1;" : "=r"(r) : "f"(x));
    return r;
}

__device__ __forceinline__ uint32_t smem_u32(const void* p) {
    uint32_t a;
    asm("{ .reg .u64 t; cvta.to.shared.u64 t, %1; cvt.u32.u64 %0, t; }" : "=r"(a) : "l"(p));
    return a;
}

// ---------------- tf32 rounding copy ----------------
__global__ void cvt_tf32_kernel(const float4* __restrict__ src, float4* __restrict__ dst, int n4)
{
    const int i = blockIdx.x * blockDim.x + threadIdx.x;
    if (i >= n4) return;
    const float4 v = src[i];
    uint4 u;
    u.x = f2tf32(v.x); u.y = f2tf32(v.y); u.z = f2tf32(v.z); u.w = f2tf32(v.w);
    dst[i] = *reinterpret_cast<float4*>(&u);
}

// ============= tf32 mma.sync GEMM, 4-stage cp.async pipeline ===============
// C[M,N] = act(A[M,K] @ B[K,N] [+bias]); A,B already tf32-rounded fp32.
// Requires: N == 1024 total with grid.x = 4 (BN=256), K % 16 == 0.
// Block 128x256x16, 8 warps 2(m) x 4(n), warp tile 64x64, m16n8k8 tf32 mma.
// SMEM (per stage): A [128 rows][20 words], B [16 rows][264 words].
#define PQ_ASTR  20
#define PQ_BSTR  264
#define PQ_AW    (128 * PQ_ASTR)            // 2560 words
#define PQ_BW    (16 * PQ_BSTR)             // 4224 words
#define PQ_STW   (PQ_AW + PQ_BW)            // 6784 words / stage
#define PQ_SMEM_BYTES (4 * PQ_STW * 4)      // 108544

template <bool RELU, bool BIAS, bool TF32OUT>
__global__ __launch_bounds__(256, 1)
void tf32_gemm_kernel(const float* __restrict__ A, const float* __restrict__ B,
                      const float* __restrict__ bias, float* __restrict__ C,
                      int M, int N, int K, int lda)
{
    extern __shared__ uint32_t sh[];
    const uint32_t sbase = smem_u32(sh);

    const int tid  = threadIdx.x;
    const int warp = tid >> 5;
    const int lane = tid & 31;
    const int g    = lane >> 2;
    const int tig  = lane & 3;
    const int bm   = blockIdx.y * 128;
    const int n0   = blockIdx.x * 256;
    const int wm   = (warp & 1) * 64;
    const int wn   = (warp >> 1) * 64;

    float acc[4][8][4];
#pragma unroll
    for (int mf = 0; mf < 4; mf++)
#pragma unroll
        for (int nf = 0; nf < 8; nf++)
#pragma unroll
            for (int q = 0; q < 4; q++) acc[mf][nf][q] = 0.f;

    const int nk = K >> 4;

    auto issue_stage = [&](int i) {
        const int slot = i & 3;
        const uint32_t sA = sbase + (uint32_t)(slot * PQ_STW) * 4u;
        const uint32_t sB = sA + PQ_AW * 4u;
        const int k0 = i * 16;
        // A: 512 16B chunks (row, kq)
#pragma unroll
        for (int j = 0; j < 2; j++) {
            const int c   = tid + j * 256;
            const int row = c >> 2, kq = c & 3;
            const float* gp = A + (size_t)(bm + row) * lda + k0 + kq * 4;
            const uint32_t sp = sA + (uint32_t)(row * PQ_ASTR + kq * 4) * 4u;
            const int sz = (bm + row < M) ? 16 : 0;
            asm volatile("cp.async.cg.shared.global [%0], [%1], 16, %2;"
                         :: "r"(sp), "l"(gp), "r"(sz));
        }
        // B: 1024 16B chunks (krow, n4)
#pragma unroll
        for (int j = 0; j < 4; j++) {
            const int c  = tid + j * 256;
            const int kr = c >> 6, n4 = c & 63;
            const float* gp = B + (size_t)(k0 + kr) * N + n0 + n4 * 4;
            const uint32_t sp = sB + (uint32_t)(kr * PQ_BSTR + n4 * 4) * 4u;
            asm volatile("cp.async.cg.shared.global [%0], [%1], 16, %2;"
                         :: "r"(sp), "l"(gp), "r"(16));
        }
    };

    auto compute = [&](int i) {
        const int slot = i & 3;
        const uint32_t* As = sh + slot * PQ_STW;
        const uint32_t* Bs = As + PQ_AW;
#pragma unroll
        for (int kc = 0; kc < 2; kc++) {
            uint32_t a[4][4], b[8][2];
#pragma unroll
            for (int mf = 0; mf < 4; mf++) {
                const int base = (wm + mf * 16 + g) * PQ_ASTR + kc * 8 + tig;
                a[mf][0] = As[base];
                a[mf][1] = As[base + 8 * PQ_ASTR];
                a[mf][2] = As[base + 4];
                a[mf][3] = As[base + 8 * PQ_ASTR + 4];
            }
#pragma unroll
            for (int nf = 0; nf < 8; nf++) {
                const int base = (kc * 8 + tig) * PQ_BSTR + wn + nf * 8 + g;
                b[nf][0] = Bs[base];
                b[nf][1] = Bs[base + 4 * PQ_BSTR];
            }
#pragma unroll
            for (int mf = 0; mf < 4; mf++)
#pragma unroll
                for (int nf = 0; nf < 8; nf++) {
                    asm volatile(
                        "mma.sync.aligned.m16n8k8.row.col.f32.tf32.tf32.f32 "
                        "{%0,%1,%2,%3}, {%4,%5,%6,%7}, {%8,%9}, {%0,%1,%2,%3};"
                        : "+f"(acc[mf][nf][0]), "+f"(acc[mf][nf][1]),
                          "+f"(acc[mf][nf][2]), "+f"(acc[mf][nf][3])
                        : "r"(a[mf][0]), "r"(a[mf][1]), "r"(a[mf][2]), "r"(a[mf][3]),
                          "r"(b[nf][0]), "r"(b[nf][1]));
                }
        }
    };

    // prologue: 3 stages in flight
    issue_stage(0); asm volatile("cp.async.commit_group;" ::: "memory");
    issue_stage(1); asm volatile("cp.async.commit_group;" ::: "memory");
    issue_stage(2); asm volatile("cp.async.commit_group;" ::: "memory");

    for (int i = 0; i < nk; i++) {
        asm volatile("cp.async.wait_group 2;" ::: "memory");
        __syncthreads();
        if (i + 3 < nk) issue_stage(i + 3);
        asm volatile("cp.async.commit_group;" ::: "memory");
        compute(i);
    }

    // epilogue
#pragma unroll
    for (int nf = 0; nf < 8; nf++) {
        const int col = n0 + wn + nf * 8 + 2 * tig;
        const float b0 = BIAS ? bias[col]     : 0.f;
        const float b1 = BIAS ? bias[col + 1] : 0.f;
#pragma unroll
        for (int mf = 0; mf < 4; mf++) {
            const int r0 = bm + wm + mf * 16 + g;
            const int r1 = r0 + 8;
            float v0 = acc[mf][nf][0] + b0;
            float v1 = acc[mf][nf][1] + b1;
            float v2 = acc[mf][nf][2] + b0;
            float v3 = acc[mf][nf][3] + b1;
            if (RELU) {
                v0 = fmaxf(v0, 0.f); v1 = fmaxf(v1, 0.f);
                v2 = fmaxf(v2, 0.f); v3 = fmaxf(v3, 0.f);
            }
            if (TF32OUT) {
                v0 = __uint_as_float(f2tf32(v0)); v1 = __uint_as_float(f2tf32(v1));
                v2 = __uint_as_float(f2tf32(v2)); v3 = __uint_as_float(f2tf32(v3));
            }
            if (r0 < M) *reinterpret_cast<float2*>(C + (size_t)r0 * N + col) = make_float2(v0, v1);
            if (r1 < M) *reinterpret_cast<float2*>(C + (size_t)r1 * N + col) = make_float2(v2, v3);
        }
    }
}

// ---------------- GEMV: y[m] = dot(X[m,:K], w) + b0 ----------------
__global__ void gemv_kernel(const float* __restrict__ X, const float* __restrict__ w,
                            const float* __restrict__ b, float* __restrict__ y,
                            int M, int K)
{
    const int row  = blockIdx.x * (blockDim.x >> 5) + (threadIdx.x >> 5);
    const int lane = threadIdx.x & 31;
    if (row >= M) return;
    const float4* x4 = reinterpret_cast<const float4*>(X + (size_t)row * K);
    const float4* w4 = reinterpret_cast<const float4*>(w);
    float acc = 0.f;
    const int K4 = K >> 2;
    for (int i = lane; i < K4; i += 32) {
        float4 a = x4[i], c = w4[i];
        acc += a.x * c.x + a.y * c.y + a.z * c.z + a.w * c.w;
    }
#pragma unroll
    for (int o = 16; o; o >>= 1) acc += __shfl_xor_sync(0xffffffffu, acc, o);
    if (lane == 0) y[row] = acc + b[0];
}

// ------------- width-bucket layer-1 contribution: Wd[b] = wemb[b]@W1d + b1 --
__global__ void wd_kernel(const float* __restrict__ wemb, const float* __restrict__ W1d,
                          const float* __restrict__ b1, float* __restrict__ Wd)
{
    const int b = blockIdx.x;
    const int h = threadIdx.x;
    float acc = b1[h];
#pragma unroll
    for (int d = 0; d < DIST_D; d++)
        acc += wemb[b * DIST_D + d] * W1d[(size_t)d * HID + h];
    Wd[(size_t)b * HID + h] = acc;
}

// -------- fused span featurization + score-MLP layer 1 ---------------------
__global__ __launch_bounds__(256)
void span_fused_kernel(const float* __restrict__ states, const float* __restrict__ embeds,
                       const float* __restrict__ wemb, const int* __restrict__ starts,
                       const int* __restrict__ widths, const float* __restrict__ attns,
                       const float* __restrict__ Pa, const float* __restrict__ Pb,
                       const float* __restrict__ Ec, const float* __restrict__ Wd,
                       float* __restrict__ gi, float* __restrict__ s1, int N)
{
    const int warp = (blockIdx.x * blockDim.x + threadIdx.x) >> 5;
    const int lane = threadIdx.x & 31;
    if (warp >= N) return;

    const int s = starts[warp];
    const int w = widths[warp];
    const int e = s + w - 1;

    // --- softmax over valid slots ---
    float a = (lane < w) ? attns[s + lane] : -INFINITY;
    float m = a;
#pragma unroll
    for (int o = 16; o; o >>= 1) m = fmaxf(m, __shfl_xor_sync(0xffffffffu, m, o));
    float ex = (lane < w) ? expf(a - m) : 0.f;
    float sum = ex;
#pragma unroll
    for (int o = 16; o; o >>= 1) sum += __shfl_xor_sync(0xffffffffu, sum, o);
    const float wgt = ex / sum;

    float* out = gi + (size_t)warp * GI_D;

    // --- g_i: start / end state copies ---
    const float4* ss = reinterpret_cast<const float4*>(states + (size_t)s * STATE_D);
    const float4* se = reinterpret_cast<const float4*>(states + (size_t)e * STATE_D);
    float4* o0 = reinterpret_cast<float4*>(out);
    float4* o1 = reinterpret_cast<float4*>(out + STATE_D);
#pragma unroll
    for (int i = lane; i < STATE_D / 4; i += 32) {
        o0[i] = ss[i];
        o1[i] = se[i];
    }

    // --- g_i: attention-pooled embeds ---
    float4* o2 = reinterpret_cast<float4*>(out + 2 * STATE_D);
#pragma unroll
    for (int i = lane; i < EMBED_D / 4; i += 32) {
        float4 acc = make_float4(0.f, 0.f, 0.f, 0.f);
        for (int j = 0; j < w; j++) {
            const float wj = __shfl_sync(0xffffffffu, wgt, j);
            const float4 ev = reinterpret_cast<const float4*>(embeds + (size_t)(s + j) * EMBED_D)[i];
            acc.x += wj * ev.x; acc.y += wj * ev.y;
            acc.z += wj * ev.z; acc.w += wj * ev.w;
        }
        o2[i] = acc;
    }

    // --- g_i: width bucket embedding ---
    const int bucket = (w >= 1) + (w >= 2) + (w >= 3) + (w >= 4) + (w >= 8);
    if (lane < DIST_D)
        out[2 * STATE_D + EMBED_D + lane] = wemb[bucket * DIST_D + lane];

    // --- layer-1: h1 = relu(Pa[s] + Pb[e] + Σ wgt_j·Ec[s+j] + Wd[bucket]) ---
    const float4* pa = reinterpret_cast<const float4*>(Pa + (size_t)s * HID);
    const float4* pb = reinterpret_cast<const float4*>(Pb + (size_t)e * HID);
    const float4* wd = reinterpret_cast<const float4*>(Wd + (size_t)bucket * HID);
    float4 acc[8];
#pragma unroll
    for (int q = 0; q < 8; q++) {
        const int i = lane + q * 32;
        const float4 va = pa[i], vb = pb[i], vd = wd[i];
        acc[q].x = va.x + vb.x + vd.x;
        acc[q].y = va.y + vb.y + vd.y;
        acc[q].z = va.z + vb.z + vd.z;
        acc[q].w = va.w + vb.w + vd.w;
    }
    for (int j = 0; j < w; j++) {
        const float wj = __shfl_sync(0xffffffffu, wgt, j);
        const float4* ec = reinterpret_cast<const float4*>(Ec + (size_t)(s + j) * HID);
#pragma unroll
        for (int q = 0; q < 8; q++) {
            const float4 ev = ec[lane + q * 32];
            acc[q].x += wj * ev.x; acc[q].y += wj * ev.y;
            acc[q].z += wj * ev.z; acc[q].w += wj * ev.w;
        }
    }
    // store s1 tf32-rounded (layer-2 reads it directly, no cvt in GEMM)
    uint4* s1r = reinterpret_cast<uint4*>(s1 + (size_t)warp * HID);
#pragma unroll
    for (int q = 0; q < 8; q++) {
        uint4 v;
        v.x = f2tf32(fmaxf(acc[q].x, 0.f));
        v.y = f2tf32(fmaxf(acc[q].y, 0.f));
        v.z = f2tf32(fmaxf(acc[q].z, 0.f));
        v.w = f2tf32(fmaxf(acc[q].w, 0.f));
        s1r[lane + q * 32] = v;
    }
}

// ---------------- launch ----------------
static void launch_cvt(const float* src, float* dst, size_t n)
{
    const int n4 = (int)(n >> 2);
    cvt_tf32_kernel<<<(n4 + 255) / 256, 256>>>(
        reinterpret_cast<const float4*>(src), reinterpret_cast<float4*>(dst), n4);
}

extern "C" void kernel_launch(void* const* d_in, const int* in_sizes, int n_in,
                              void* d_out, int out_size)
{
    const float* states = (const float*)d_in[0];
    const float* embeds = (const float*)d_in[1];
    const float* aW1 = (const float*)d_in[2];  const float* ab1 = (const float*)d_in[3];
    const float* aW2 = (const float*)d_in[4];  const float* ab2 = (const float*)d_in[5];
    const float* aW3 = (const float*)d_in[6];  const float* ab3 = (const float*)d_in[7];
    const float* sW1 = (const float*)d_in[8];  const float* sb1 = (const float*)d_in[9];
    const float* sW2 = (const float*)d_in[10]; const float* sb2 = (const float*)d_in[11];
    const float* sW3 = (const float*)d_in[12]; const float* sb3 = (const float*)d_in[13];
    const float* wemb = (const float*)d_in[14];
    const int* sstarts = (const int*)d_in[15];
    const int* swidths = (const int*)d_in[16];
    const int N = in_sizes[15];   // 40915 spans

    float* out    = (float*)d_out;
    float* gi     = out;                         // [N, 2580]
    float* scores = out + (size_t)N * GI_D;      // [N]

    float *h1, *h2, *attns, *pa, *pb, *ec, *wd, *s1, *s2;
    float *states_t, *embeds_t, *aW1_t, *aW2_t, *sW1_t, *sW2_t;
    cudaGetSymbolAddress((void**)&h1,    g_h1);
    cudaGetSymbolAddress((void**)&h2,    g_h2);
    cudaGetSymbolAddress((void**)&attns, g_attns);
    cudaGetSymbolAddress((void**)&pa,    g_pa);
    cudaGetSymbolAddress((void**)&pb,    g_pb);
    cudaGetSymbolAddress((void**)&ec,    g_ec);
    cudaGetSymbolAddress((void**)&wd,    g_wd);
    cudaGetSymbolAddress((void**)&s1,    g_s1);
    cudaGetSymbolAddress((void**)&s2,    g_s2);
    cudaGetSymbolAddress((void**)&states_t, g_states_t);
    cudaGetSymbolAddress((void**)&embeds_t, g_embeds_t);
    cudaGetSymbolAddress((void**)&aW1_t, g_aW1_t);
    cudaGetSymbolAddress((void**)&aW2_t, g_aW2_t);
    cudaGetSymbolAddress((void**)&sW1_t, g_sW1_t);
    cudaGetSymbolAddress((void**)&sW2_t, g_sW2_t);

    cudaFuncSetAttribute(tf32_gemm_kernel<true,  true,  true >,
                         cudaFuncAttributeMaxDynamicSharedMemorySize, PQ_SMEM_BYTES);
    cudaFuncSetAttribute(tf32_gemm_kernel<true,  true,  false>,
                         cudaFuncAttributeMaxDynamicSharedMemorySize, PQ_SMEM_BYTES);
    cudaFuncSetAttribute(tf32_gemm_kernel<false, false, false>,
                         cudaFuncAttributeMaxDynamicSharedMemorySize, PQ_SMEM_BYTES);

    // 0) one-time tf32 rounding of GEMM operands
    launch_cvt(states, states_t, (size_t)T_TOK * STATE_D);
    launch_cvt(embeds, embeds_t, (size_t)T_TOK * EMBED_D);
    launch_cvt(aW1,    aW1_t,    (size_t)STATE_D * HID);
    launch_cvt(aW2,    aW2_t,    (size_t)HID * HID);
    launch_cvt(sW1,    sW1_t,    (size_t)2560 * HID);
    launch_cvt(sW2,    sW2_t,    (size_t)HID * HID);

    // 1) attention MLP over tokens
    {
        dim3 grid(HID / 256, T_TOK / 128);
        tf32_gemm_kernel<true, true, true><<<grid, 256, PQ_SMEM_BYTES>>>(
            states_t, aW1_t, ab1, h1, T_TOK, HID, STATE_D, STATE_D);
        tf32_gemm_kernel<true, true, false><<<grid, 256, PQ_SMEM_BYTES>>>(
            h1, aW2_t, ab2, h2, T_TOK, HID, HID, HID);
        gemv_kernel<<<(T_TOK * 32 + 255) / 256, 256>>>(h2, aW3, ab3, attns, T_TOK, HID);
    }

    // 2) token-level layer-1 precomputation: Pa, Pb, Ec
    {
        dim3 grid(HID / 256, T_TOK / 128);
        tf32_gemm_kernel<false, false, false><<<grid, 256, PQ_SMEM_BYTES>>>(
            states_t, sW1_t, nullptr, pa, T_TOK, HID, STATE_D, STATE_D);
        tf32_gemm_kernel<false, false, false><<<grid, 256, PQ_SMEM_BYTES>>>(
            states_t, sW1_t + (size_t)STATE_D * HID, nullptr, pb, T_TOK, HID, STATE_D, STATE_D);
        tf32_gemm_kernel<false, false, false><<<grid, 256, PQ_SMEM_BYTES>>>(
            embeds_t, sW1_t + (size_t)2 * STATE_D * HID, nullptr, ec, T_TOK, HID, EMBED_D, EMBED_D);
        wd_kernel<<<NBUCK, HID>>>(wemb, sW1 + (size_t)(GI_D - DIST_D) * HID, sb1, wd);
    }

    // 3) fused span featurization + layer 1 -> g_i (d_out) and s1 (tf32)
    {
        const int warps_per_block = 8;
        const int blocks = (N + warps_per_block - 1) / warps_per_block;
        span_fused_kernel<<<blocks, warps_per_block * 32>>>(
            states, embeds, wemb, sstarts, swidths, attns, pa, pb, ec, wd, gi, s1, N);
    }

    // 4) layer 2 + final gemv
    {
        dim3 grid(HID / 256, (N + 127) / 128);
        tf32_gemm_kernel<true, true, false><<<grid, 256, PQ_SMEM_BYTES>>>(
            s1, sW2_t, sb2, s2, N, HID, HID, HID);
        gemv_kernel<<<(N * 32 + 255) / 256, 256>>>(s2, sW3, sb3, scores, N, HID);
    }
}

// round 13
// speedup vs baseline: 1.8065x; 1.8065x over previous
#include <cuda_runtime.h>
#include <cuda_fp16.h>
#include <math.h>
#include <stdint.h>

// ---------------- problem constants ----------------
#define T_TOK   4096
#define STATE_D 1024
#define EMBED_D 512
#define DIST_D  20
#define HID     1024
#define GI_D    2580      // 2*STATE_D + EMBED_D + DIST_D
#define MAX_W   10
#define NBUCK   9

// ---------------- scratch (static device globals; no allocs) --------------
__device__ float g_h1[(size_t)T_TOK * HID];
__device__ float g_h2[(size_t)T_TOK * HID];
__device__ float g_attns[T_TOK];
__device__ float g_pa[(size_t)T_TOK * HID];
__device__ float g_pb[(size_t)T_TOK * HID];
__device__ float g_ec[(size_t)T_TOK * HID];
__device__ float g_wd[(size_t)NBUCK * HID];
__device__ float g_s1[(size_t)40960 * HID];
__device__ float g_s2[(size_t)40960 * HID];

__device__ __forceinline__ uint32_t pack_h2(float x, float y) {
    __half2 h = __float22half2_rn(make_float2(x, y));
    return *reinterpret_cast<uint32_t*>(&h);
}

// ============= fp16 mma.sync GEMM, fragment-permuted SMEM ==================
// C[M,N] = act(A[M,K] @ B[K,N] [+bias]); A,B fp32 in GMEM, fp16 in SMEM.
// Requires: N == 1024 with grid.x = 4 (BN=256), K % 16 == 0.
// Block tile 128x256x16, 8 warps 2(m) x 4(n), warp tile 64x64, m16n8k16.
// SMEM fragment layout (per buffer):
//   A: [8 groups fr][32 lanes][4 words a0..a3]           = 1024 u32 (4 KB)
//   B: [32 groups nf][32 lanes][2 words b0,b1]           = 2048 u32 (8 KB)
template <bool RELU, bool BIAS>
__global__ __launch_bounds__(256, 1)
void hgemm_kernel(const float* __restrict__ A, const float* __restrict__ B,
                  const float* __restrict__ bias, float* __restrict__ C,
                  int M, int N, int K, int lda)
{
    __shared__ uint32_t As[2][1024];
    __shared__ uint32_t Bs[2][2048];

    const int tid  = threadIdx.x;
    const int warp = tid >> 5;
    const int lane = tid & 31;
    const int g    = lane >> 2;
    const int tig  = lane & 3;
    const int bm   = blockIdx.y * 128;
    const int n0   = blockIdx.x * 256;
    const int wm   = (warp & 1) * 64;
    const int wn   = (warp >> 1) * 64;
    const int wmg  = wm >> 4;   // fragment-group offsets
    const int wng  = wn >> 3;

    float acc[4][8][4];
#pragma unroll
    for (int mf = 0; mf < 4; mf++)
#pragma unroll
        for (int nf = 0; nf < 8; nf++)
#pragma unroll
            for (int q = 0; q < 4; q++) acc[mf][nf][q] = 0.f;

    // fill assignments
    const int afr = tid >> 5;          // A: group fr 0..7
    const int aln = tid & 31;          //    lane
    const int agg = aln >> 2;
    const int atg = aln & 3;
    const int bnf = tid >> 3;          // B: group nf 0..31
    const int bsub = tid & 7;          //    column-within-group

    float2 a_st[4];
    float  b_st[16];

    auto ldgA = [&](int k0) {
        const int r0 = bm + afr * 16 + agg;
        const int r1 = r0 + 8;
        const float* p = A + (size_t)r0 * lda + k0 + 2 * atg;
        const float* p1 = p + (size_t)8 * lda;
        const float2 z = make_float2(0.f, 0.f);
        a_st[0] = (r0 < M) ? *reinterpret_cast<const float2*>(p)      : z;
        a_st[1] = (r1 < M) ? *reinterpret_cast<const float2*>(p1)     : z;
        a_st[2] = (r0 < M) ? *reinterpret_cast<const float2*>(p + 8)  : z;
        a_st[3] = (r1 < M) ? *reinterpret_cast<const float2*>(p1 + 8) : z;
    };
    auto stsA = [&](int buf) {
        uint4 u;
        u.x = pack_h2(a_st[0].x, a_st[0].y);
        u.y = pack_h2(a_st[1].x, a_st[1].y);
        u.z = pack_h2(a_st[2].x, a_st[2].y);
        u.w = pack_h2(a_st[3].x, a_st[3].y);
        *reinterpret_cast<uint4*>(&As[buf][tid * 4]) = u;
    };
    auto ldgB = [&](int k0) {
        const float* p = B + (size_t)k0 * N + n0 + bnf * 8 + bsub;
#pragma unroll
        for (int k = 0; k < 16; k++) b_st[k] = p[(size_t)k * N];
    };
    auto stsB = [&](int buf) {
        uint4 u0, u1;
        u0.x = pack_h2(b_st[0], b_st[1]);   // b0 (tt=0)
        u0.y = pack_h2(b_st[8], b_st[9]);   // b1 (tt=0)
        u0.z = pack_h2(b_st[2], b_st[3]);   // b0 (tt=1)
        u0.w = pack_h2(b_st[10], b_st[11]); // b1 (tt=1)
        u1.x = pack_h2(b_st[4], b_st[5]);
        u1.y = pack_h2(b_st[12], b_st[13]);
        u1.z = pack_h2(b_st[6], b_st[7]);
        u1.w = pack_h2(b_st[14], b_st[15]);
        uint32_t* d = &Bs[buf][bnf * 64 + bsub * 8];
        *reinterpret_cast<uint4*>(d)     = u0;
        *reinterpret_cast<uint4*>(d + 4) = u1;
    };
    auto compute = [&](int buf) {
        uint4 a[4];
        uint2 b[8];
#pragma unroll
        for (int mf = 0; mf < 4; mf++)
            a[mf] = *reinterpret_cast<const uint4*>(&As[buf][(wmg + mf) * 128 + lane * 4]);
#pragma unroll
        for (int nf = 0; nf < 8; nf++)
            b[nf] = *reinterpret_cast<const uint2*>(&Bs[buf][(wng + nf) * 64 + lane * 2]);
#pragma unroll
        for (int mf = 0; mf < 4; mf++)
#pragma unroll
            for (int nf = 0; nf < 8; nf++) {
                asm volatile(
                    "mma.sync.aligned.m16n8k16.row.col.f32.f16.f16.f32 "
                    "{%0,%1,%2,%3}, {%4,%5,%6,%7}, {%8,%9}, {%0,%1,%2,%3};"
                    : "+f"(acc[mf][nf][0]), "+f"(acc[mf][nf][1]),
                      "+f"(acc[mf][nf][2]), "+f"(acc[mf][nf][3])
                    : "r"(a[mf].x), "r"(a[mf].y), "r"(a[mf].z), "r"(a[mf].w),
                      "r"(b[nf].x), "r"(b[nf].y));
            }
    };

    ldgA(0); ldgB(0);
    stsA(0); stsB(0);
    __syncthreads();

    const int nk = K >> 4;
    for (int i = 0; i < nk; i++) {
        const int buf = i & 1;
        if (i + 1 < nk) { ldgA((i + 1) * 16); ldgB((i + 1) * 16); }
        compute(buf);
        if (i + 1 < nk) {
            stsA(buf ^ 1); stsB(buf ^ 1);
            __syncthreads();
        }
    }

    // epilogue (same fragment->C mapping as m16n8k8: c0,c1 @ (g, 2tig), c2,c3 @ (g+8))
#pragma unroll
    for (int nf = 0; nf < 8; nf++) {
        const int col = n0 + wn + nf * 8 + 2 * tig;
        const float b0 = BIAS ? bias[col]     : 0.f;
        const float b1 = BIAS ? bias[col + 1] : 0.f;
#pragma unroll
        for (int mf = 0; mf < 4; mf++) {
            const int r0 = bm + wm + mf * 16 + g;
            const int r1 = r0 + 8;
            float v0 = acc[mf][nf][0] + b0;
            float v1 = acc[mf][nf][1] + b1;
            float v2 = acc[mf][nf][2] + b0;
            float v3 = acc[mf][nf][3] + b1;
            if (RELU) {
                v0 = fmaxf(v0, 0.f); v1 = fmaxf(v1, 0.f);
                v2 = fmaxf(v2, 0.f); v3 = fmaxf(v3, 0.f);
            }
            if (r0 < M) *reinterpret_cast<float2*>(C + (size_t)r0 * N + col) = make_float2(v0, v1);
            if (r1 < M) *reinterpret_cast<float2*>(C + (size_t)r1 * N + col) = make_float2(v2, v3);
        }
    }
}

// ---------------- GEMV: y[m] = dot(X[m,:K], w) + b0 ----------------
__global__ void gemv_kernel(const float* __restrict__ X, const float* __restrict__ w,
                            const float* __restrict__ b, float* __restrict__ y,
                            int M, int K)
{
    const int row  = blockIdx.x * (blockDim.x >> 5) + (threadIdx.x >> 5);
    const int lane = threadIdx.x & 31;
    if (row >= M) return;
    const float4* x4 = reinterpret_cast<const float4*>(X + (size_t)row * K);
    const float4* w4 = reinterpret_cast<const float4*>(w);
    float acc = 0.f;
    const int K4 = K >> 2;
    for (int i = lane; i < K4; i += 32) {
        float4 a = x4[i], c = w4[i];
        acc += a.x * c.x + a.y * c.y + a.z * c.z + a.w * c.w;
    }
#pragma unroll
    for (int o = 16; o; o >>= 1) acc += __shfl_xor_sync(0xffffffffu, acc, o);
    if (lane == 0) y[row] = acc + b[0];
}

// ------------- width-bucket layer-1 contribution: Wd[b] = wemb[b]@W1d + b1 --
__global__ void wd_kernel(const float* __restrict__ wemb, const float* __restrict__ W1d,
                          const float* __restrict__ b1, float* __restrict__ Wd)
{
    const int b = blockIdx.x;
    const int h = threadIdx.x;
    float acc = b1[h];
#pragma unroll
    for (int d = 0; d < DIST_D; d++)
        acc += wemb[b * DIST_D + d] * W1d[(size_t)d * HID + h];
    Wd[(size_t)b * HID + h] = acc;
}

// -------- fused span featurization + score-MLP layer 1 ---------------------
__global__ __launch_bounds__(256)
void span_fused_kernel(const float* __restrict__ states, const float* __restrict__ embeds,
                       const float* __restrict__ wemb, const int* __restrict__ starts,
                       const int* __restrict__ widths, const float* __restrict__ attns,
                       const float* __restrict__ Pa, const float* __restrict__ Pb,
                       const float* __restrict__ Ec, const float* __restrict__ Wd,
                       float* __restrict__ gi, float* __restrict__ s1, int N)
{
    const int warp = (blockIdx.x * blockDim.x + threadIdx.x) >> 5;
    const int lane = threadIdx.x & 31;
    if (warp >= N) return;

    const int s = starts[warp];
    const int w = widths[warp];
    const int e = s + w - 1;

    // --- softmax over valid slots ---
    float a = (lane < w) ? attns[s + lane] : -INFINITY;
    float m = a;
#pragma unroll
    for (int o = 16; o; o >>= 1) m = fmaxf(m, __shfl_xor_sync(0xffffffffu, m, o));
    float ex = (lane < w) ? expf(a - m) : 0.f;
    float sum = ex;
#pragma unroll
    for (int o = 16; o; o >>= 1) sum += __shfl_xor_sync(0xffffffffu, sum, o);
    const float wgt = ex / sum;

    float* out = gi + (size_t)warp * GI_D;

    // --- g_i: start / end state copies ---
    const float4* ss = reinterpret_cast<const float4*>(states + (size_t)s * STATE_D);
    const float4* se = reinterpret_cast<const float4*>(states + (size_t)e * STATE_D);
    float4* o0 = reinterpret_cast<float4*>(out);
    float4* o1 = reinterpret_cast<float4*>(out + STATE_D);
#pragma unroll
    for (int i = lane; i < STATE_D / 4; i += 32) {
        o0[i] = ss[i];
        o1[i] = se[i];
    }

    // --- g_i: attention-pooled embeds ---
    float4* o2 = reinterpret_cast<float4*>(out + 2 * STATE_D);
#pragma unroll
    for (int i = lane; i < EMBED_D / 4; i += 32) {
        float4 acc = make_float4(0.f, 0.f, 0.f, 0.f);
        for (int j = 0; j < w; j++) {
            const float wj = __shfl_sync(0xffffffffu, wgt, j);
            const float4 ev = reinterpret_cast<const float4*>(embeds + (size_t)(s + j) * EMBED_D)[i];
            acc.x += wj * ev.x; acc.y += wj * ev.y;
            acc.z += wj * ev.z; acc.w += wj * ev.w;
        }
        o2[i] = acc;
    }

    // --- g_i: width bucket embedding ---
    const int bucket = (w >= 1) + (w >= 2) + (w >= 3) + (w >= 4) + (w >= 8);
    if (lane < DIST_D)
        out[2 * STATE_D + EMBED_D + lane] = wemb[bucket * DIST_D + lane];

    // --- layer-1: h1 = relu(Pa[s] + Pb[e] + Σ wgt_j·Ec[s+j] + Wd[bucket]) ---
    const float4* pa = reinterpret_cast<const float4*>(Pa + (size_t)s * HID);
    const float4* pb = reinterpret_cast<const float4*>(Pb + (size_t)e * HID);
    const float4* wd = reinterpret_cast<const float4*>(Wd + (size_t)bucket * HID);
    float4 acc[8];
#pragma unroll
    for (int q = 0; q < 8; q++) {
        const int i = lane + q * 32;
        const float4 va = pa[i], vb = pb[i], vd = wd[i];
        acc[q].x = va.x + vb.x + vd.x;
        acc[q].y = va.y + vb.y + vd.y;
        acc[q].z = va.z + vb.z + vd.z;
        acc[q].w = va.w + vb.w + vd.w;
    }
    for (int j = 0; j < w; j++) {
        const float wj = __shfl_sync(0xffffffffu, wgt, j);
        const float4* ec = reinterpret_cast<const float4*>(Ec + (size_t)(s + j) * HID);
#pragma unroll
        for (int q = 0; q < 8; q++) {
            const float4 ev = ec[lane + q * 32];
            acc[q].x += wj * ev.x; acc[q].y += wj * ev.y;
            acc[q].z += wj * ev.z; acc[q].w += wj * ev.w;
        }
    }
    float4* s1r = reinterpret_cast<float4*>(s1 + (size_t)warp * HID);
#pragma unroll
    for (int q = 0; q < 8; q++) {
        float4 v = acc[q];
        v.x = fmaxf(v.x, 0.f); v.y = fmaxf(v.y, 0.f);
        v.z = fmaxf(v.z, 0.f); v.w = fmaxf(v.w, 0.f);
        s1r[lane + q * 32] = v;
    }
}

// ---------------- launch ----------------
extern "C" void kernel_launch(void* const* d_in, const int* in_sizes, int n_in,
                              void* d_out, int out_size)
{
    const float* states = (const float*)d_in[0];
    const float* embeds = (const float*)d_in[1];
    const float* aW1 = (const float*)d_in[2];  const float* ab1 = (const float*)d_in[3];
    const float* aW2 = (const float*)d_in[4];  const float* ab2 = (const float*)d_in[5];
    const float* aW3 = (const float*)d_in[6];  const float* ab3 = (const float*)d_in[7];
    const float* sW1 = (const float*)d_in[8];  const float* sb1 = (const float*)d_in[9];
    const float* sW2 = (const float*)d_in[10]; const float* sb2 = (const float*)d_in[11];
    const float* sW3 = (const float*)d_in[12]; const float* sb3 = (const float*)d_in[13];
    const float* wemb = (const float*)d_in[14];
    const int* sstarts = (const int*)d_in[15];
    const int* swidths = (const int*)d_in[16];
    const int N = in_sizes[15];   // 40915 spans

    float* out    = (float*)d_out;
    float* gi     = out;                         // [N, 2580]
    float* scores = out + (size_t)N * GI_D;      // [N]

    float *h1, *h2, *attns, *pa, *pb, *ec, *wd, *s1, *s2;
    cudaGetSymbolAddress((void**)&h1,    g_h1);
    cudaGetSymbolAddress((void**)&h2,    g_h2);
    cudaGetSymbolAddress((void**)&attns, g_attns);
    cudaGetSymbolAddress((void**)&pa,    g_pa);
    cudaGetSymbolAddress((void**)&pb,    g_pb);
    cudaGetSymbolAddress((void**)&ec,    g_ec);
    cudaGetSymbolAddress((void**)&wd,    g_wd);
    cudaGetSymbolAddress((void**)&s1,    g_s1);
    cudaGetSymbolAddress((void**)&s2,    g_s2);

    // 1) attention MLP over tokens (fp16 tensor cores, fp32 accumulate)
    {
        dim3 grid(4, T_TOK / 128);
        hgemm_kernel<true, true><<<grid, 256>>>(states, aW1, ab1, h1, T_TOK, HID, STATE_D, STATE_D);
        hgemm_kernel<true, true><<<grid, 256>>>(h1, aW2, ab2, h2, T_TOK, HID, HID, HID);
        gemv_kernel<<<(T_TOK * 32 + 255) / 256, 256>>>(h2, aW3, ab3, attns, T_TOK, HID);
    }

    // 2) token-level layer-1 precomputation: Pa, Pb, Ec
    {
        dim3 grid(4, T_TOK / 128);
        hgemm_kernel<false, false><<<grid, 256>>>(
            states, sW1, nullptr, pa, T_TOK, HID, STATE_D, STATE_D);
        hgemm_kernel<false, false><<<grid, 256>>>(
            states, sW1 + (size_t)STATE_D * HID, nullptr, pb, T_TOK, HID, STATE_D, STATE_D);
        hgemm_kernel<false, false><<<grid, 256>>>(
            embeds, sW1 + (size_t)2 * STATE_D * HID, nullptr, ec, T_TOK, HID, EMBED_D, EMBED_D);
        wd_kernel<<<NBUCK, HID>>>(wemb, sW1 + (size_t)(GI_D - DIST_D) * HID, sb1, wd);
    }

    // 3) fused span featurization + layer 1 -> g_i (d_out) and s1
    {
        const int warps_per_block = 8;
        const int blocks = (N + warps_per_block - 1) / warps_per_block;
        span_fused_kernel<<<blocks, warps_per_block * 32>>>(
            states, embeds, wemb, sstarts, swidths, attns, pa, pb, ec, wd, gi, s1, N);
    }

    // 4) layer 2 + final gemv
    {
        dim3 grid(4, (N + 127) / 128);
        hgemm_kernel<true, true><<<grid, 256>>>(s1, sW2, sb2, s2, N, HID, HID, HID);
        gemv_kernel<<<(N * 32 + 255) / 256, 256>>>(s2, sW3, sb3, scores, N, HID);
    }
}